// round 15
// baseline (speedup 1.0000x reference)
#include <cuda_runtime.h>
#include <cuda_bf16.h>
#include <cstdint>

// Problem constants
#define NN 8192
#define RR 32
#define TN 128                    // M-tile per block
#define SPLITK 64
#define KCHUNK (NN / SPLITK)      // 128
#define NSTG16 (KCHUNK / 16)      // 8 k16 stages
#define NBUF 4                    // A ring buffers
#define THREADS 128               // 4 warps; warp tile = 32M x 32N

// Scratch: z stages only (split-K reduced atomically into z)
__device__ float g_z[4 * RR * NN];          // z stages [k][r][n]

// B smem row: 128 k * 2B = 256 bytes, XOR-16B swizzle by (row&7)
#define BROW_BYTES 256
#define A_STAGE_BYTES (TN * 64)   // 8 KB per k16 buffer

__device__ __forceinline__ uint32_t cvt_bf16x2(float hi, float lo) {
    uint32_t r;
    asm("cvt.rn.bf16x2.f32 %0,%1,%2;" : "=r"(r) : "f"(hi), "f"(lo));
    return r;
}
// split 2 fp32 -> packed bf16 hi-pair and lo-pair (element x in low half)
__device__ __forceinline__ void split2(float x, float y, uint32_t& w, uint32_t& l) {
    w = cvt_bf16x2(y, x);
    float h0 = __uint_as_float(w << 16);
    float h1 = __uint_as_float(w & 0xFFFF0000u);
    l = cvt_bf16x2(y - h1, x - h0);
}
__device__ __forceinline__ void ldsm4(uint32_t& r0, uint32_t& r1, uint32_t& r2,
                                      uint32_t& r3, uint32_t a) {
    asm volatile("ldmatrix.sync.aligned.m8n8.x4.shared.b16 {%0,%1,%2,%3},[%4];"
                 : "=r"(r0), "=r"(r1), "=r"(r2), "=r"(r3) : "r"(a));
}
__device__ __forceinline__ void mma16816(float& c0, float& c1, float& c2, float& c3,
                                         uint32_t a0, uint32_t a1, uint32_t a2, uint32_t a3,
                                         uint32_t b0, uint32_t b1) {
    asm volatile(
        "mma.sync.aligned.m16n8k16.row.col.f32.bf16.bf16.f32 "
        "{%0,%1,%2,%3},{%4,%5,%6,%7},{%8,%9},{%0,%1,%2,%3};"
        : "+f"(c0), "+f"(c1), "+f"(c2), "+f"(c3)
        : "r"(a0), "r"(a1), "r"(a2), "r"(a3), "r"(b0), "r"(b1));
}
__device__ __forceinline__ void cp16(uint32_t dst, const void* src) {
    asm volatile("cp.async.cg.shared.global [%0], [%1], 16;" :: "r"(dst), "l"(src));
}
__device__ __forceinline__ float2 lds64(uint32_t addr) {
    float2 v;
    asm volatile("ld.shared.v2.f32 {%0,%1},[%2];" : "=f"(v.x), "=f"(v.y) : "r"(addr));
    return v;
}

// ---------------------------------------------------------------------------
// Stage 0: transpose x[B,N,G] -> z0[r][n], r = b*8+g
// ---------------------------------------------------------------------------
__global__ void transpose_kernel(const float* __restrict__ x, float* __restrict__ z0) {
    int idx = blockIdx.x * 256 + threadIdx.x;
    int n = idx & (NN - 1);
    int r = idx >> 13;
    int b = r >> 3;
    int g = r & 7;
    z0[idx] = x[((b << 13) + n) * 8 + g];
}

// ---------------------------------------------------------------------------
// Zero-fill z stages 1..3 (atomic accumulation targets)
// ---------------------------------------------------------------------------
__global__ void zero_kernel(float* __restrict__ p) {
    ((float4*)p)[blockIdx.x * 256 + threadIdx.x] = make_float4(0.f, 0.f, 0.f, 0.f);
}

// ---------------------------------------------------------------------------
// bf16x3 mma.sync GEMM, 4 warps, warp tile 32M x 32N, WARP-LOCAL pipelines:
// each warp cp.asyncs exactly the 32 A-rows it consumes -> no block barriers
// in the main loop (wait_group + __syncwarp only).
//   zn[r][n0+m] += sum_{k in chunk sp} S[n0+m][k] * z[r][k]
// ---------------------------------------------------------------------------
__global__ void __launch_bounds__(THREADS, 4)
gemm_kernel(const float* __restrict__ A, const float* __restrict__ B,
            float* __restrict__ zn) {
    __shared__ __align__(128) char smA[NBUF * A_STAGE_BYTES];  // 32 KB (ring; reused as c-stage)
    __shared__ __align__(128) char smBH[RR * BROW_BYTES];      // 8 KB
    __shared__ __align__(128) char smBL[RR * BROW_BYTES];      // 8 KB

    const int tid = threadIdx.x;
    const int wid = tid >> 5;       // 0..3
    const int lid = tid & 31;
    const int nb  = blockIdx.x;     // 0..63
    const int sp  = blockIdx.y;     // 0..SPLITK-1
    const int n0  = nb * TN;
    const int m0  = sp * KCHUNK;

    const uint32_t smA_u = (uint32_t)__cvta_generic_to_shared(smA);

    // ---------------- A cp.async mapping: WARP-LOCAL rows -------------------
    // warp w owns rows 32w..32w+31; lane: row_local rl = lid>>2 (+8p), granule ag.
    const int rl = lid >> 2;              // 0..7
    const int ag = lid & 3;               // 16B granule within 64B row
    const int arow0 = 32 * wid + rl;      // first of 4 rows (step 8)
    const float* Asrc = A + (size_t)(n0 + arow0) * NN + m0 + ag * 4;
    const uint32_t a_sw = ((uint32_t)(ag ^ (rl & 3))) << 4;   // row&3 == rl&3
    const uint32_t ad0 = (uint32_t)arow0 * 64u + a_sw;

#define ISSUE_A(S)                                                              \
    {                                                                           \
        const uint32_t bo = smA_u + (uint32_t)((S) & (NBUF - 1)) * A_STAGE_BYTES; \
        const float* srcp = Asrc + (S) * 16;                                    \
        cp16(bo + ad0,              srcp);                                      \
        cp16(bo + ad0 + 8u * 64u,   srcp + (size_t)8 * NN);                     \
        cp16(bo + ad0 + 16u * 64u,  srcp + (size_t)16 * NN);                    \
        cp16(bo + ad0 + 24u * 64u,  srcp + (size_t)24 * NN);                    \
    }

    // prologue: stage 0 first (DRAM starts while we stage B)
    ISSUE_A(0);
    asm volatile("cp.async.commit_group;");

    // ---------------- one-time B staging: fp32 -> bf16 hi/lo smem ----------
    {
        const int row   = tid >> 2;          // 0..31
        const int kbase = (tid & 3) << 3;    // 0,8,16,24
        const float* bp = B + (size_t)row * NN + m0 + kbase;
        const uint32_t ph = ((uint32_t)row & 7u) << 4;   // 16B-granule XOR phase
#pragma unroll
        for (int i = 0; i < 4; i++) {
            const int k = kbase + 32 * i;
            float4 v0 = *(const float4*)(bp + 32 * i);
            float4 v1 = *(const float4*)(bp + 32 * i + 4);
            uint32_t h0, l0, h1, l1, h2, l2, h3, l3;
            split2(v0.x, v0.y, h0, l0);
            split2(v0.z, v0.w, h1, l1);
            split2(v1.x, v1.y, h2, l2);
            split2(v1.z, v1.w, h3, l3);
            uint32_t off = (uint32_t)row * BROW_BYTES + (((uint32_t)k * 2u) ^ ph);
            *(uint4*)(smBH + off) = make_uint4(h0, h1, h2, h3);
            *(uint4*)(smBL + off) = make_uint4(l0, l1, l2, l3);
        }
    }

    // prologue: stages 1, 2
    ISSUE_A(1);
    asm volatile("cp.async.commit_group;");
    ISSUE_A(2);
    asm volatile("cp.async.commit_group;");

    __syncthreads();   // B visible to all warps (the ONLY pre-epilogue block barrier)

    // ---------------- fragment lane mappings --------------------------------
    const int rg = lid >> 2;            // 0..7
    const int qh = (lid & 3) >> 1;      // granule low bit
    const uint32_t qb = (uint32_t)(lid & 1) * 8u;

    const int brow0 = ((lid >> 4) << 3) + (lid & 7);   // n-tiles 0/1
    const int brow1 = 16 + brow0;                      // n-tiles 2/3
    const int bhalf = (lid >> 3) & 1;
    const uint32_t smbh = (uint32_t)__cvta_generic_to_shared(smBH);
    const uint32_t smbl = (uint32_t)__cvta_generic_to_shared(smBL);
    const uint32_t bo0base = (uint32_t)brow0 * BROW_BYTES;
    const uint32_t bo1base = (uint32_t)brow1 * BROW_BYTES;
    const uint32_t bph0 = ((uint32_t)brow0 & 7u) << 4;
    const uint32_t bph1 = ((uint32_t)brow1 & 7u) << 4;

    // warp owns M rows 32*wid .. 32*wid+31 (two m16 groups)
    const int mrow0 = 32 * wid + rg;          // group 0 rows (and +8)
    const uint32_t x0 = (((uint32_t)qh ^ (uint32_t)(mrow0 & 3)) << 4) + qb;
    const uint32_t x2 = ((((uint32_t)qh + 2u) ^ (uint32_t)(mrow0 & 3)) << 4) + qb;

    float c[2][4][4];
#pragma unroll
    for (int h2 = 0; h2 < 2; h2++)
#pragma unroll
        for (int j = 0; j < 4; j++)
#pragma unroll
            for (int e = 0; e < 4; e++) c[h2][j][e] = 0.0f;

#pragma unroll
    for (int s = 0; s < NSTG16; s++) {
        // warp-local readiness: my lanes' copies of groups <= s complete
        asm volatile("cp.async.wait_group 2;" ::: "memory");
        __syncwarp();

        if (s + 3 < NSTG16) ISSUE_A(s + 3);
        asm volatile("cp.async.commit_group;");

        const uint32_t abuf = smA_u + (uint32_t)(s & (NBUF - 1)) * A_STAGE_BYTES;
        const uint32_t arow_base = abuf + (uint32_t)mrow0 * 64u;

        // B fragments (shared by both m-groups)
        const uint32_t kb = (uint32_t)(s * 32 + bhalf * 16);
        const uint32_t o0 = bo0base + (kb ^ bph0);
        const uint32_t o1 = bo1base + (kb ^ bph1);
        uint32_t bh[8], bl[8];
        ldsm4(bh[0], bh[1], bh[2], bh[3], smbh + o0);
        ldsm4(bh[4], bh[5], bh[6], bh[7], smbh + o1);
        ldsm4(bl[0], bl[1], bl[2], bl[3], smbl + o0);
        ldsm4(bl[4], bl[5], bl[6], bl[7], smbl + o1);

#pragma unroll
        for (int h2 = 0; h2 < 2; h2++) {
            const uint32_t a_row_off = arow_base + (uint32_t)(h2 * 16) * 64u;
            float2 fa0 = lds64(a_row_off + x0);
            float2 fa1 = lds64(a_row_off + 8u * 64u + x0);
            float2 fa2 = lds64(a_row_off + x2);
            float2 fa3 = lds64(a_row_off + 8u * 64u + x2);

            uint32_t ah[4], al[4];
            split2(fa0.x, fa0.y, ah[0], al[0]);
            split2(fa1.x, fa1.y, ah[1], al[1]);
            split2(fa2.x, fa2.y, ah[2], al[2]);
            split2(fa3.x, fa3.y, ah[3], al[3]);

#pragma unroll
            for (int j = 0; j < 4; j++) {
                mma16816(c[h2][j][0], c[h2][j][1], c[h2][j][2], c[h2][j][3],
                         ah[0], ah[1], ah[2], ah[3], bh[2 * j], bh[2 * j + 1]);
                mma16816(c[h2][j][0], c[h2][j][1], c[h2][j][2], c[h2][j][3],
                         ah[0], ah[1], ah[2], ah[3], bl[2 * j], bl[2 * j + 1]);
                mma16816(c[h2][j][0], c[h2][j][1], c[h2][j][2], c[h2][j][3],
                         al[0], al[1], al[2], al[3], bh[2 * j], bh[2 * j + 1]);
            }
        }
    }
#undef ISSUE_A

    // ---------------- epilogue: stage c-tile to smem, coalesced red.v2 ------
    __syncthreads();   // all warps done; ring reusable as c-stage
    float* cstage = (float*)smA;
    {
        const int kc = (lid & 3) << 1;
#pragma unroll
        for (int h2 = 0; h2 < 2; h2++) {
            const int mloc = 32 * wid + 16 * h2 + rg;
#pragma unroll
            for (int j = 0; j < 4; j++) {
                int r = 8 * j + kc;
                cstage[r * 132 + mloc]           = c[h2][j][0];
                cstage[(r + 1) * 132 + mloc]     = c[h2][j][1];
                cstage[r * 132 + mloc + 8]       = c[h2][j][2];
                cstage[(r + 1) * 132 + mloc + 8] = c[h2][j][3];
            }
        }
    }
    __syncthreads();
#pragma unroll
    for (int p = 0; p < 16; p++) {
        int idx = tid + THREADS * p;    // 0..2047 float2 slots
        int r  = idx >> 6;              // 0..31
        int ch = (idx & 63) * 2;        // col 0..126 step 2
        float2 v = *(const float2*)(cstage + r * 132 + ch);
        float* dst = zn + (size_t)r * NN + n0 + ch;
        asm volatile("red.global.add.v2.f32 [%0], {%1, %2};"
                     :: "l"(dst), "f"(v.x), "f"(v.y) : "memory");
    }
}

// ---------------------------------------------------------------------------
// Final projection (torch-faithful raw-reshape mapping)
// ---------------------------------------------------------------------------
__global__ void final_kernel(const float* __restrict__ z, const float* __restrict__ W,
                             const float* __restrict__ bias, float* __restrict__ y) {
    __shared__ float Ws[256];
    __shared__ float bs[8];
    int t = threadIdx.x;
    Ws[t] = W[t];
    if (t < 8) bs[t] = bias[t];
    __syncthreads();

    int idx = blockIdx.x * 256 + t;
    int n = idx & (NN - 1);
    int b = idx >> 13;
    int k0 = n >> 11;
    int g0 = (n >> 8) & 7;
    const float* zp = z + ((size_t)(k0 * RR + b * 8 + g0) << 13) + ((n & 255) << 5);

    float bb = bs[n >> 10];
    float acc[8];
#pragma unroll
    for (int f = 0; f < 8; f++) acc[f] = bb;

#pragma unroll
    for (int jq = 0; jq < 8; jq++) {
        float4 zv = *(const float4*)(zp + 4 * jq);
#pragma unroll
        for (int e = 0; e < 4; e++) {
            float zs = (e == 0) ? zv.x : (e == 1) ? zv.y : (e == 2) ? zv.z : zv.w;
            int j = 4 * jq + e;
#pragma unroll
            for (int f = 0; f < 8; f++) acc[f] += zs * Ws[8 * j + f];
        }
    }

    float4* yo = (float4*)(y + (size_t)idx * 8);
    yo[0] = make_float4(acc[0], acc[1], acc[2], acc[3]);
    yo[1] = make_float4(acc[4], acc[5], acc[6], acc[7]);
}

// ---------------------------------------------------------------------------
extern "C" void kernel_launch(void* const* d_in, const int* in_sizes, int n_in,
                              void* d_out, int out_size) {
    const float* x    = (const float*)d_in[0];
    const float* S    = (const float*)d_in[1];
    const float* W    = (const float*)d_in[2];
    const float* bias = (const float*)d_in[3];
    float* y = (float*)d_out;

    float* zbuf;
    cudaGetSymbolAddress((void**)&zbuf, g_z);

    transpose_kernel<<<1024, 256>>>(x, zbuf);
    // zero z stages 1..3 (3 * RR * NN floats = 196608 float4)
    zero_kernel<<<768, 256>>>(zbuf + RR * NN);

    for (int k = 0; k < 3; k++) {
        gemm_kernel<<<dim3(64, SPLITK), THREADS>>>(S + (size_t)k * NN * NN,
                                                   zbuf + (size_t)k * RR * NN,
                                                   zbuf + (size_t)(k + 1) * RR * NN);
    }

    final_kernel<<<128, 256>>>(zbuf, W, bias, y);
}